// round 2
// baseline (speedup 1.0000x reference)
#include <cuda_runtime.h>
#include <cuda_bf16.h>
#include <mma.h>

using namespace nvcuda;

#define LDP 68          // padded leading dim (multiple of 4 floats, odd bank stride)
#define NTHREADS 256

namespace {
constexpr int C    = 256;   // channels
constexpr int CQK  = 32;    // q/k channels
constexpr int P    = 64;    // pixels per 8x8 window
constexpr int SMEM_FLOATS = 2 * C * LDP + 2 * CQK * LDP + P * LDP;  // 43520 floats = 174080 B
}

using FragA  = wmma::fragment<wmma::matrix_a, 16, 16, 8, wmma::precision::tf32, wmma::row_major>;
using FragAc = wmma::fragment<wmma::matrix_a, 16, 16, 8, wmma::precision::tf32, wmma::col_major>;
using FragB  = wmma::fragment<wmma::matrix_b, 16, 16, 8, wmma::precision::tf32, wmma::row_major>;
using FragBc = wmma::fragment<wmma::matrix_b, 16, 16, 8, wmma::precision::tf32, wmma::col_major>;
using FragC  = wmma::fragment<wmma::accumulator, 16, 16, 8, float>;

#define CVT(frag)                                                   \
    {                                                               \
        _Pragma("unroll")                                           \
        for (int _i = 0; _i < (frag).num_elements; ++_i)            \
            (frag).x[_i] = wmma::__float_to_tf32((frag).x[_i]);     \
    }

__global__ __launch_bounds__(NTHREADS, 1)
void eff_attn_kernel(const float* __restrict__ x,
                     const float* __restrict__ wq,
                     const float* __restrict__ bq,
                     const float* __restrict__ wk,
                     const float* __restrict__ bk,
                     const float* __restrict__ wv,
                     const float* __restrict__ bv,
                     const float* __restrict__ gamma,
                     float* __restrict__ out)
{
    extern __shared__ float sm[];
    float* s_xw = sm;                    // [256][LDP] window input (kept for residual)
    float* s_y  = s_xw + C * LDP;        // [256][LDP] y = xw @ attn^T, later out
    float* s_q  = s_y  + C * LDP;        // [32][LDP]
    float* s_k  = s_q  + CQK * LDP;      // [32][LDP]
    float* s_sc = s_k  + CQK * LDP;      // [64][LDP] scores / attn

    const int tid  = threadIdx.x;
    const int warp = tid >> 5;

    // window index -> (b, hw, ww); Hw = Ww = 32
    const int n  = blockIdx.x;
    const int b  = n >> 10;
    const int hw = (n >> 5) & 31;
    const int ww = n & 31;
    // x[b, c, hw*8+py, ww*8+px], H = W = 256
    const size_t gbase = ((size_t)b * C) * 65536 + (size_t)(hw * 8) * 256 + (size_t)(ww * 8);

    // ---- stage window: xw[c][p], p = py*8+px ----
    #pragma unroll 4
    for (int idx = tid; idx < C * P; idx += NTHREADS) {
        const int c = idx >> 6, p = idx & 63;
        s_xw[c * LDP + p] = x[gbase + (size_t)c * 65536 + (size_t)(p >> 3) * 256 + (p & 7)];
    }
    __syncthreads();

    // ---- Phase A: q = wq@xw, k = wk@xw  ([32,64] each) ----
    {
        const int r  = warp >> 2;     // 0..1 : 16-row strip of q/k
        const int cc = warp & 3;      // 0..3 : 16-col strip
        FragC accq, acck;
        wmma::fill_fragment(accq, 0.0f);
        wmma::fill_fragment(acck, 0.0f);
        const float* aq = wq + r * 16 * C;
        const float* ak = wk + r * 16 * C;
        for (int kk = 0; kk < C / 8; ++kk) {
            FragB fb;
            wmma::load_matrix_sync(fb, s_xw + kk * 8 * LDP + cc * 16, LDP);
            CVT(fb);
            FragA fa;
            wmma::load_matrix_sync(fa, aq + kk * 8, C);
            CVT(fa);
            wmma::mma_sync(accq, fa, fb, accq);
            wmma::load_matrix_sync(fa, ak + kk * 8, C);
            CVT(fa);
            wmma::mma_sync(acck, fa, fb, acck);
        }
        wmma::store_matrix_sync(s_q + r * 16 * LDP + cc * 16, accq, LDP, wmma::mem_row_major);
        wmma::store_matrix_sync(s_k + r * 16 * LDP + cc * 16, acck, LDP, wmma::mem_row_major);
    }
    __syncthreads();
    // add q/k biases (zero in practice, but honor the inputs)
    for (int idx = tid; idx < CQK * P; idx += NTHREADS) {
        const int c = idx >> 6, p = idx & 63;
        s_q[c * LDP + p] += bq[c];
        s_k[c * LDP + p] += bk[c];
    }
    __syncthreads();

    // ---- Phase B: scores[p,q] = <Q[:,p], K[:,q]> / 8 ----
    {
        const int r  = warp >> 1;        // 0..3 : p strip
        const int c0 = (warp & 1) * 2;   // col strips c0, c0+1
        FragC a0, a1;
        wmma::fill_fragment(a0, 0.0f);
        wmma::fill_fragment(a1, 0.0f);
        for (int kk = 0; kk < CQK / 8; ++kk) {
            FragAc fa;   // A = Q^T via col-major view of q[c][p]
            wmma::load_matrix_sync(fa, s_q + kk * 8 * LDP + r * 16, LDP);
            CVT(fa);
            FragB fb;
            wmma::load_matrix_sync(fb, s_k + kk * 8 * LDP + c0 * 16, LDP);
            CVT(fb);
            wmma::mma_sync(a0, fa, fb, a0);
            wmma::load_matrix_sync(fb, s_k + kk * 8 * LDP + (c0 + 1) * 16, LDP);
            CVT(fb);
            wmma::mma_sync(a1, fa, fb, a1);
        }
        #pragma unroll
        for (int i = 0; i < a0.num_elements; ++i) { a0.x[i] *= 0.125f; a1.x[i] *= 0.125f; }
        wmma::store_matrix_sync(s_sc + r * 16 * LDP + c0 * 16,       a0, LDP, wmma::mem_row_major);
        wmma::store_matrix_sync(s_sc + r * 16 * LDP + (c0 + 1) * 16, a1, LDP, wmma::mem_row_major);
    }
    __syncthreads();

    // ---- Phase C: row softmax over q ----
    if (tid < P) {
        float* row = s_sc + tid * LDP;
        float m = row[0];
        #pragma unroll
        for (int j = 1; j < P; ++j) m = fmaxf(m, row[j]);
        float s = 0.0f;
        #pragma unroll
        for (int j = 0; j < P; ++j) { const float e = __expf(row[j] - m); row[j] = e; s += e; }
        const float inv = 1.0f / s;
        #pragma unroll
        for (int j = 0; j < P; ++j) row[j] *= inv;
    }
    __syncthreads();

    // ---- Phase D: y = xw @ attn^T  ([256,64]) ----
    {
        FragC acc[2][4];
        #pragma unroll
        for (int r2 = 0; r2 < 2; ++r2)
            #pragma unroll
            for (int nn = 0; nn < 4; ++nn) wmma::fill_fragment(acc[r2][nn], 0.0f);
        for (int kk = 0; kk < P / 8; ++kk) {
            FragBc fb[4];   // B[k,n] = attn[n_base+n][kk*8+k] via col-major view
            #pragma unroll
            for (int nn = 0; nn < 4; ++nn) {
                wmma::load_matrix_sync(fb[nn], s_sc + nn * 16 * LDP + kk * 8, LDP);
                CVT(fb[nn]);
            }
            #pragma unroll
            for (int r2 = 0; r2 < 2; ++r2) {
                FragA fa;
                wmma::load_matrix_sync(fa, s_xw + (warp * 2 + r2) * 16 * LDP + kk * 8, LDP);
                CVT(fa);
                #pragma unroll
                for (int nn = 0; nn < 4; ++nn)
                    wmma::mma_sync(acc[r2][nn], fa, fb[nn], acc[r2][nn]);
            }
        }
        #pragma unroll
        for (int r2 = 0; r2 < 2; ++r2)
            #pragma unroll
            for (int nn = 0; nn < 4; ++nn)
                wmma::store_matrix_sync(s_y + (warp * 2 + r2) * 16 * LDP + nn * 16,
                                        acc[r2][nn], LDP, wmma::mem_row_major);
    }
    __syncthreads();

    // ---- Phase E: out = wv @ y  ([256,64]) ----
    {
        FragC acc[2][4];
        #pragma unroll
        for (int r2 = 0; r2 < 2; ++r2)
            #pragma unroll
            for (int nn = 0; nn < 4; ++nn) wmma::fill_fragment(acc[r2][nn], 0.0f);
        for (int kk = 0; kk < C / 8; ++kk) {
            FragB fb[4];
            #pragma unroll
            for (int nn = 0; nn < 4; ++nn) {
                wmma::load_matrix_sync(fb[nn], s_y + kk * 8 * LDP + nn * 16, LDP);
                CVT(fb[nn]);
            }
            #pragma unroll
            for (int r2 = 0; r2 < 2; ++r2) {
                FragA fa;
                wmma::load_matrix_sync(fa, wv + (size_t)(warp * 2 + r2) * 16 * C + kk * 8, C);
                CVT(fa);
                #pragma unroll
                for (int nn = 0; nn < 4; ++nn)
                    wmma::mma_sync(acc[r2][nn], fa, fb[nn], acc[r2][nn]);
            }
        }
        __syncthreads();   // all reads of s_y done before overwrite
        #pragma unroll
        for (int r2 = 0; r2 < 2; ++r2)
            #pragma unroll
            for (int nn = 0; nn < 4; ++nn)
                wmma::store_matrix_sync(s_y + (warp * 2 + r2) * 16 * LDP + nn * 16,
                                        acc[r2][nn], LDP, wmma::mem_row_major);
    }
    __syncthreads();

    // ---- epilogue: gamma * (out + bv) + x ----
    const float g = gamma[0];
    #pragma unroll 4
    for (int idx = tid; idx < C * P; idx += NTHREADS) {
        const int c = idx >> 6, p = idx & 63;
        const float v = g * (s_y[c * LDP + p] + bv[c]) + s_xw[c * LDP + p];
        out[gbase + (size_t)c * 65536 + (size_t)(p >> 3) * 256 + (p & 7)] = v;
    }
}

extern "C" void kernel_launch(void* const* d_in, const int* in_sizes, int n_in,
                              void* d_out, int out_size)
{
    const float* x  = (const float*)d_in[0];
    const float* wq = (const float*)d_in[1];
    const float* bq = (const float*)d_in[2];
    const float* wk = (const float*)d_in[3];
    const float* bk = (const float*)d_in[4];
    const float* wv = (const float*)d_in[5];
    const float* bv = (const float*)d_in[6];
    const float* gm = (const float*)d_in[7];
    float* out = (float*)d_out;

    const int B = in_sizes[0] / (256 * 256 * 256);   // 4
    const int grid = B * 32 * 32;                    // 4096 windows

    const size_t smem = (size_t)SMEM_FLOATS * sizeof(float);  // 174080 B
    cudaFuncSetAttribute(eff_attn_kernel,
                         cudaFuncAttributeMaxDynamicSharedMemorySize, (int)smem);
    eff_attn_kernel<<<grid, NTHREADS, smem>>>(x, wq, bq, wk, bk, wv, bv, gm, out);
}

// round 9
// speedup vs baseline: 1.0184x; 1.0184x over previous
#include <cuda_runtime.h>
#include <cuda_bf16.h>
#include <mma.h>

using namespace nvcuda;

#define NTHREADS 512
#define LDB 72      // bf16 array leading dim
#define LDF 68      // f32 array leading dim

namespace {
constexpr int C    = 256;
constexpr int CQK  = 32;
constexpr int P    = 64;
constexpr int KSTEP = 16;
constexpr int NKC   = C / KSTEP;   // 16 k-steps over channels

// smem byte offsets
constexpr int OFF_XH = 0;          // bf16 [256][72]  36864 B
constexpr int OFF_XL = 36864;      // bf16 [256][72]  36864 B
constexpr int OFF_WT = 73728;      // 2 bufs x (4096 hi + 4096 lo) bf16 = 32768 B
constexpr int OFF_Q  = 106496;     // f32 [32][68]   8704 B
constexpr int OFF_K  = 115200;     // f32 [32][68]   8704 B
constexpr int OFF_SC = 123904;     // f32 [64][68]  17408 B
constexpr int OFF_V  = 141312;     // f32 [256][68] 69632 B  (V, later out)
constexpr int SMEM_BYTES = 210944; // < 232448 dynamic limit -> 1 CTA/SM
}

// weight scratch: rows 0-31 wq, 32-63 wk, 64-319 wv (row-major, 256 cols)
__device__ __nv_bfloat16 g_wh[320 * 256];
__device__ __nv_bfloat16 g_wl[320 * 256];

__global__ void prep_split(const float* __restrict__ wq,
                           const float* __restrict__ wk,
                           const float* __restrict__ wv)
{
    int i = blockIdx.x * blockDim.x + threadIdx.x;
    if (i >= 320 * 256) return;
    float w;
    if (i < 32 * 256)       w = wq[i];
    else if (i < 64 * 256)  w = wk[i - 32 * 256];
    else                    w = wv[i - 64 * 256];
    __nv_bfloat16 h = __float2bfloat16(w);
    g_wh[i] = h;
    g_wl[i] = __float2bfloat16(w - __bfloat162float(h));
}

using FragAh = wmma::fragment<wmma::matrix_a, 16, 16, 16, __nv_bfloat16, wmma::row_major>;
using FragBh = wmma::fragment<wmma::matrix_b, 16, 16, 16, __nv_bfloat16, wmma::row_major>;
using FragCh = wmma::fragment<wmma::accumulator, 16, 16, 16, float>;

using FragAt  = wmma::fragment<wmma::matrix_a, 16, 16, 8, wmma::precision::tf32, wmma::row_major>;
using FragAct = wmma::fragment<wmma::matrix_a, 16, 16, 8, wmma::precision::tf32, wmma::col_major>;
using FragBt  = wmma::fragment<wmma::matrix_b, 16, 16, 8, wmma::precision::tf32, wmma::row_major>;
using FragBct = wmma::fragment<wmma::matrix_b, 16, 16, 8, wmma::precision::tf32, wmma::col_major>;
using FragCt  = wmma::fragment<wmma::accumulator, 16, 16, 8, float>;

#define CVT(frag)                                                   \
    {                                                               \
        _Pragma("unroll")                                           \
        for (int _i = 0; _i < (frag).num_elements; ++_i)            \
            (frag).x[_i] = wmma::__float_to_tf32((frag).x[_i]);     \
    }

// stage a [nrows x 16] hi/lo weight tile (k-step kk) into s_wt buffer `buf`
__device__ __forceinline__ void stage_wt(__nv_bfloat16* wt, int buf,
                                         int rowbase, int nrows, int kk, int tid)
{
    __nv_bfloat16* dh = wt + buf * 8192;
    __nv_bfloat16* dl = dh + 4096;
    for (int i = tid; i < nrows * 2; i += NTHREADS) {
        const int row = i >> 1, seg = i & 1;
        const uint4* sh = reinterpret_cast<const uint4*>(g_wh + (rowbase + row) * 256 + kk * 16) + seg;
        const uint4* sl = reinterpret_cast<const uint4*>(g_wl + (rowbase + row) * 256 + kk * 16) + seg;
        reinterpret_cast<uint4*>(dh + row * 16)[seg] = *sh;
        reinterpret_cast<uint4*>(dl + row * 16)[seg] = *sl;
    }
}

__global__ __launch_bounds__(NTHREADS, 1)
void eff_attn_kernel(const float* __restrict__ x,
                     const float* __restrict__ bq,
                     const float* __restrict__ bk,
                     const float* __restrict__ bv,
                     const float* __restrict__ gamma,
                     float* __restrict__ out)
{
    extern __shared__ char smraw[];
    __nv_bfloat16* s_xh = reinterpret_cast<__nv_bfloat16*>(smraw + OFF_XH);
    __nv_bfloat16* s_xl = reinterpret_cast<__nv_bfloat16*>(smraw + OFF_XL);
    __nv_bfloat16* s_wt = reinterpret_cast<__nv_bfloat16*>(smraw + OFF_WT);
    float* s_q  = reinterpret_cast<float*>(smraw + OFF_Q);
    float* s_k  = reinterpret_cast<float*>(smraw + OFF_K);
    float* s_sc = reinterpret_cast<float*>(smraw + OFF_SC);
    float* s_v  = reinterpret_cast<float*>(smraw + OFF_V);

    const int tid  = threadIdx.x;
    const int warp = tid >> 5;
    const int lane = tid & 31;

    const int n  = blockIdx.x;
    const int b  = n >> 10;
    const int hw = (n >> 5) & 31;
    const int ww = n & 31;
    const size_t gbase = ((size_t)b * C) * 65536 + (size_t)(hw * 8) * 256 + (size_t)(ww * 8);

    // ---- stage window, split into bf16 hi/lo ----
    #pragma unroll 4
    for (int i = tid; i < C * P; i += NTHREADS) {
        const int c = i >> 6, p = i & 63;
        const float f = x[gbase + (size_t)c * 65536 + (size_t)(p >> 3) * 256 + (p & 7)];
        const __nv_bfloat16 h = __float2bfloat16(f);
        s_xh[c * LDB + p] = h;
        s_xl[c * LDB + p] = __float2bfloat16(f - __bfloat162float(h));
    }
    __syncthreads();

    // ---- Phase A: q = wq@xw, k = wk@xw (compensated bf16, [32,64] each) ----
    {
        const int mat = warp >> 3;          // 0 = q, 1 = k
        const int r   = (warp >> 2) & 1;    // 16-row strip
        const int cc  = warp & 3;           // 16-col strip
        FragCh acc;
        wmma::fill_fragment(acc, 0.0f);
        stage_wt(s_wt, 0, 0, 64, 0, tid);
        __syncthreads();
        for (int kk = 0; kk < NKC; ++kk) {
            if (kk + 1 < NKC) stage_wt(s_wt, (kk + 1) & 1, 0, 64, kk + 1, tid);
            const __nv_bfloat16* wh = s_wt + (kk & 1) * 8192 + (mat * 32 + r * 16) * 16;
            const __nv_bfloat16* wl = wh + 4096;
            FragAh fah, fal;
            wmma::load_matrix_sync(fah, wh, 16);
            wmma::load_matrix_sync(fal, wl, 16);
            FragBh fbh, fbl;
            wmma::load_matrix_sync(fbh, s_xh + kk * 16 * LDB + cc * 16, LDB);
            wmma::load_matrix_sync(fbl, s_xl + kk * 16 * LDB + cc * 16, LDB);
            wmma::mma_sync(acc, fah, fbh, acc);
            wmma::mma_sync(acc, fah, fbl, acc);
            wmma::mma_sync(acc, fal, fbh, acc);
            __syncthreads();
        }
        float* dst = (mat ? s_k : s_q) + r * 16 * LDF + cc * 16;
        wmma::store_matrix_sync(dst, acc, LDF, wmma::mem_row_major);
    }
    __syncthreads();   // q/k stores visible before cross-warp bias read-modify-write
    for (int i = tid; i < CQK * P; i += NTHREADS) {
        const int c = i >> 6, p = i & 63;
        s_q[c * LDF + p] += bq[c];
        s_k[c * LDF + p] += bk[c];
    }

    // ---- Phase V: V = wv@xw (compensated bf16, [256,64]) ----
    {
        const int rw = warp >> 1;   // 0..7 : 32-row group
        const int cg = warp & 1;    // 0..1 : 32-col group
        FragCh acc[2][2];
        #pragma unroll
        for (int r2 = 0; r2 < 2; ++r2)
            #pragma unroll
            for (int n2 = 0; n2 < 2; ++n2) wmma::fill_fragment(acc[r2][n2], 0.0f);
        stage_wt(s_wt, 0, 64, 256, 0, tid);
        __syncthreads();   // also orders the bias writes above before Phase B reads
        for (int kk = 0; kk < NKC; ++kk) {
            if (kk + 1 < NKC) stage_wt(s_wt, (kk + 1) & 1, 64, 256, kk + 1, tid);
            FragAh fah[2], fal[2];
            #pragma unroll
            for (int r2 = 0; r2 < 2; ++r2) {
                const __nv_bfloat16* wh = s_wt + (kk & 1) * 8192 + (rw * 32 + r2 * 16) * 16;
                wmma::load_matrix_sync(fah[r2], wh, 16);
                wmma::load_matrix_sync(fal[r2], wh + 4096, 16);
            }
            #pragma unroll
            for (int n2 = 0; n2 < 2; ++n2) {
                FragBh fbh, fbl;
                wmma::load_matrix_sync(fbh, s_xh + kk * 16 * LDB + cg * 32 + n2 * 16, LDB);
                wmma::load_matrix_sync(fbl, s_xl + kk * 16 * LDB + cg * 32 + n2 * 16, LDB);
                #pragma unroll
                for (int r2 = 0; r2 < 2; ++r2) {
                    wmma::mma_sync(acc[r2][n2], fah[r2], fbh, acc[r2][n2]);
                    wmma::mma_sync(acc[r2][n2], fah[r2], fbl, acc[r2][n2]);
                    wmma::mma_sync(acc[r2][n2], fal[r2], fbh, acc[r2][n2]);
                }
            }
            __syncthreads();
        }
        #pragma unroll
        for (int r2 = 0; r2 < 2; ++r2)
            #pragma unroll
            for (int n2 = 0; n2 < 2; ++n2)
                wmma::store_matrix_sync(s_v + (rw * 32 + r2 * 16) * LDF + cg * 32 + n2 * 16,
                                        acc[r2][n2], LDF, wmma::mem_row_major);
    }
    __syncthreads();

    // ---- Phase B: scores[p,q] = <Q[:,p], K[:,q]> / 8  (tf32) ----
    {
        const int r  = warp >> 2;   // 0..3
        const int cb = warp & 3;    // 0..3
        FragCt acc;
        wmma::fill_fragment(acc, 0.0f);
        for (int kk = 0; kk < CQK / 8; ++kk) {
            FragAct fa;
            wmma::load_matrix_sync(fa, s_q + kk * 8 * LDF + r * 16, LDF);
            CVT(fa);
            FragBt fb;
            wmma::load_matrix_sync(fb, s_k + kk * 8 * LDF + cb * 16, LDF);
            CVT(fb);
            wmma::mma_sync(acc, fa, fb, acc);
        }
        #pragma unroll
        for (int i = 0; i < acc.num_elements; ++i) acc.x[i] *= 0.125f;
        wmma::store_matrix_sync(s_sc + r * 16 * LDF + cb * 16, acc, LDF, wmma::mem_row_major);
    }
    __syncthreads();

    // ---- Phase C: row softmax (one warp per 4 rows) ----
    {
        #pragma unroll
        for (int rr = 0; rr < 4; ++rr) {
            float* rp = s_sc + (warp * 4 + rr) * LDF;
            float v0 = rp[lane], v1 = rp[lane + 32];
            float m = fmaxf(v0, v1);
            #pragma unroll
            for (int o = 16; o > 0; o >>= 1) m = fmaxf(m, __shfl_xor_sync(0xffffffffu, m, o));
            const float e0 = __expf(v0 - m), e1 = __expf(v1 - m);
            float s = e0 + e1;
            #pragma unroll
            for (int o = 16; o > 0; o >>= 1) s += __shfl_xor_sync(0xffffffffu, s, o);
            const float inv = __frcp_rn(s);
            rp[lane]      = e0 * inv;
            rp[lane + 32] = e1 * inv;
        }
    }
    __syncthreads();

    // ---- Apply: out = V @ attn^T  (tf32, K=64); bv folded out since attn rows sum to 1 ----
    {
        const int rw = warp >> 1;   // 0..7 : 32 rows
        const int cg = warp & 1;    // 0..1 : 32 cols
        FragCt acc[2][2];
        #pragma unroll
        for (int r2 = 0; r2 < 2; ++r2)
            #pragma unroll
            for (int n2 = 0; n2 < 2; ++n2) wmma::fill_fragment(acc[r2][n2], 0.0f);
        for (int kk = 0; kk < P / 8; ++kk) {
            FragAt fa[2];
            #pragma unroll
            for (int r2 = 0; r2 < 2; ++r2) {
                wmma::load_matrix_sync(fa[r2], s_v + (rw * 32 + r2 * 16) * LDF + kk * 8, LDF);
                CVT(fa[r2]);
            }
            #pragma unroll
            for (int n2 = 0; n2 < 2; ++n2) {
                FragBct fb;   // B[k=q][n=p] = attn[p][q] via col-major view
                wmma::load_matrix_sync(fb, s_sc + (cg * 32 + n2 * 16) * LDF + kk * 8, LDF);
                CVT(fb);
                #pragma unroll
                for (int r2 = 0; r2 < 2; ++r2)
                    wmma::mma_sync(acc[r2][n2], fa[r2], fb, acc[r2][n2]);
            }
        }
        __syncthreads();   // everyone done reading s_v before overwrite
        #pragma unroll
        for (int r2 = 0; r2 < 2; ++r2)
            #pragma unroll
            for (int n2 = 0; n2 < 2; ++n2)
                wmma::store_matrix_sync(s_v + (rw * 32 + r2 * 16) * LDF + cg * 32 + n2 * 16,
                                        acc[r2][n2], LDF, wmma::mem_row_major);
    }
    __syncthreads();

    // ---- epilogue: gamma * (out + bv) + x ----
    const float g = gamma[0];
    #pragma unroll 4
    for (int i = tid; i < C * P; i += NTHREADS) {
        const int c = i >> 6, p = i & 63;
        const size_t ga = gbase + (size_t)c * 65536 + (size_t)(p >> 3) * 256 + (p & 7);
        out[ga] = g * (s_v[c * LDF + p] + bv[c]) + x[ga];
    }
}

extern "C" void kernel_launch(void* const* d_in, const int* in_sizes, int n_in,
                              void* d_out, int out_size)
{
    const float* x  = (const float*)d_in[0];
    const float* wq = (const float*)d_in[1];
    const float* bq = (const float*)d_in[2];
    const float* wk = (const float*)d_in[3];
    const float* bk = (const float*)d_in[4];
    const float* wv = (const float*)d_in[5];
    const float* bv = (const float*)d_in[6];
    const float* gm = (const float*)d_in[7];
    float* out = (float*)d_out;

    prep_split<<<(320 * 256 + 255) / 256, 256>>>(wq, wk, wv);

    const int B = in_sizes[0] / (256 * 256 * 256);   // 4
    const int grid = B * 32 * 32;                    // 4096 windows

    cudaFuncSetAttribute(eff_attn_kernel,
                         cudaFuncAttributeMaxDynamicSharedMemorySize, SMEM_BYTES);
    eff_attn_kernel<<<grid, NTHREADS, SMEM_BYTES>>>(x, bq, bk, bv, gm, out);
}